// round 10
// baseline (speedup 1.0000x reference)
#include <cuda_runtime.h>
#include <cuda_fp16.h>

#define BATCH 2
#define CH 512
#define FH 50
#define FW 75
#define HW (FH * FW)          // 3750
#define PH 8
#define PW 8
#define NTHREADS 256          // 2 channels per thread
#define OUT_PER_ROI (CH * 7 * 7)            // 25088 elements
#define SMEM_BYTES (OUT_PER_ROI * 2)        // 50176 bytes (fp16 staging)
#define SPATIAL_SCALE (1.0f / 16.0f)

// NHWC fp16 scratch: 2 * 3750 * 512 * 2B = 7.68 MB (deep in L2)
__device__ __half g_feat_hwc[BATCH * HW * CH];

// ---------------------------------------------------------------------------
// Kernel 1: NCHW fp32 -> NHWC fp16 transpose.
// ---------------------------------------------------------------------------
__global__ void transpose_nchw_nhwc(const float* __restrict__ in) {
    __shared__ float tile[32][33];
    const int b   = blockIdx.z;
    const int hw0 = blockIdx.x * 32;
    const int c0  = blockIdx.y * 32;

    const float* src = in + (size_t)b * CH * HW;
    __half*      dst = g_feat_hwc + (size_t)b * HW * CH;

    #pragma unroll
    for (int t = 0; t < 32; t += 8) {
        int c  = c0 + threadIdx.y + t;
        int hw = hw0 + threadIdx.x;
        if (hw < HW)
            tile[threadIdx.y + t][threadIdx.x] = src[(size_t)c * HW + hw];
    }
    __syncthreads();

    // Write phase: half2 over channel pairs, coalesced.
    const int tid = threadIdx.y * 32 + threadIdx.x;   // 0..255
    #pragma unroll
    for (int t = 0; t < 2; t++) {
        const int idx    = t * 256 + tid;   // 0..511
        const int hw_off = idx >> 4;        // 0..31
        const int cpair  = idx & 15;        // 0..15
        const int hw     = hw0 + hw_off;
        if (hw < HW) {
            __half2 v = __floats2half2_rn(tile[2 * cpair][hw_off],
                                          tile[2 * cpair + 1][hw_off]);
            *(__half2*)(dst + (size_t)hw * CH + c0 + 2 * cpair) = v;
        }
    }
}

// ---------------------------------------------------------------------------
// Kernel 2: one CTA per roi, 256 threads = 2 consecutive channels each.
// half2 loads (LDG.32) on NHWC fp16; fp32 interpolation + pooling; output
// staged in fp16 smem (conflict-free), copied out coalesced as fp32.
// ---------------------------------------------------------------------------
__global__ __launch_bounds__(NTHREADS, 4)
void roi_plus_avg_kernel(const float* __restrict__ rois,
                         float* __restrict__ out) {
    extern __shared__ __half s_out[];   // OUT_PER_ROI halves

    const int n  = blockIdx.x;
    const int c0 = threadIdx.x * 2;     // channels c0, c0+1

    __shared__ int   s_hs[PH], s_ws[PW];
    __shared__ float s_hr[PH], s_wr[PW];
    __shared__ int   s_hv[PH], s_wv[PW];
    __shared__ int   s_b;

    if (threadIdx.x < PH) {
        const int i = threadIdx.x;
        const float x1 = rois[n * 5 + 1] * SPATIAL_SCALE;
        const float y1 = rois[n * 5 + 2] * SPATIAL_SCALE;
        const float x2 = rois[n * 5 + 3] * SPATIAL_SCALE;
        const float y2 = rois[n * 5 + 4] * SPATIAL_SCALE;
        const float roi_w = fmaxf(x2 - x1 + 1.0f, 0.0f);
        const float roi_h = fmaxf(y2 - y1 + 1.0f, 0.0f);
        const float bin_h = roi_h * (1.0f / (PH - 1));
        const float bin_w = roi_w * (1.0f / (PW - 1));

        const float hh = y1 + (float)i * bin_h;
        const float ww = x1 + (float)i * bin_w;

        s_hv[i] = (hh >= 0.0f) && (hh < (float)FH);
        s_wv[i] = (ww >= 0.0f) && (ww < (float)FW);

        int hs = (int)floorf(hh);
        int ws = (int)floorf(ww);
        hs = min(max(hs, 0), FH - 2);
        ws = min(max(ws, 0), FW - 2);
        s_hs[i] = hs;
        s_ws[i] = ws;
        s_hr[i] = hh - (float)hs;
        s_wr[i] = ww - (float)ws;

        if (i == 0) s_b = (int)rois[n * 5 + 0];
    }
    __syncthreads();

    const __half* fb = g_feat_hwc + (size_t)s_b * HW * CH + c0;

    float2 prev[PW];
    float2 cur[PW];

    #pragma unroll
    for (int i = 0; i < PH; i++) {
        const int   hs = s_hs[i];
        const float hr = s_hr[i];
        const bool  hv = (s_hv[i] != 0);
        const __half* r0 = fb + (size_t)(hs * FW) * CH;
        const __half* r1 = r0 + (size_t)FW * CH;

        #pragma unroll
        for (int j = 0; j < PW; j++) {
            float2 v = make_float2(0.0f, 0.0f);
            if (hv && s_wv[j]) {
                const int   ws = s_ws[j];
                const float wr = s_wr[j];
                const float2 ul = __half22float2(__ldg((const __half2*)(r0 + (size_t)ws * CH)));
                const float2 ur = __half22float2(__ldg((const __half2*)(r0 + (size_t)(ws + 1) * CH)));
                const float2 ll = __half22float2(__ldg((const __half2*)(r1 + (size_t)ws * CH)));
                const float2 lr = __half22float2(__ldg((const __half2*)(r1 + (size_t)(ws + 1) * CH)));
                const float tx = fmaf(ur.x - ul.x, wr, ul.x);
                const float bx = fmaf(lr.x - ll.x, wr, ll.x);
                const float ty = fmaf(ur.y - ul.y, wr, ul.y);
                const float by = fmaf(lr.y - ll.y, wr, ll.y);
                v.x = fmaf(bx - tx, hr, tx);
                v.y = fmaf(by - ty, hr, ty);
            }
            cur[j] = v;
        }

        if (i > 0) {
            // fp16 staging, per-channel stride 49 halves -> odd word stride,
            // conflict-free STS.16
            __half* o0 = s_out + c0 * 49 + (i - 1) * 7;
            __half* o1 = o0 + 49;
            #pragma unroll
            for (int j = 0; j < 7; j++) {
                o0[j] = __float2half_rn(0.25f * (prev[j].x + prev[j + 1].x +
                                                 cur[j].x  + cur[j + 1].x));
                o1[j] = __float2half_rn(0.25f * (prev[j].y + prev[j + 1].y +
                                                 cur[j].y  + cur[j + 1].y));
            }
        }
        #pragma unroll
        for (int j = 0; j < PW; j++) prev[j] = cur[j];
    }

    __syncthreads();

    // Coalesced copy-out: read 8 halves (uint4), write 2 float4.
    // 25088 halves = 3136 uint4 chunks.
    float*        dstf = out + (size_t)n * OUT_PER_ROI;
    const uint4*  src  = (const uint4*)s_out;
    for (int idx = threadIdx.x; idx < OUT_PER_ROI / 8; idx += NTHREADS) {
        const uint4 u = src[idx];
        const float2 a = __half22float2(*(const __half2*)&u.x);
        const float2 b = __half22float2(*(const __half2*)&u.y);
        const float2 c = __half22float2(*(const __half2*)&u.z);
        const float2 d = __half22float2(*(const __half2*)&u.w);
        float4* o4 = (float4*)(dstf + idx * 8);
        o4[0] = make_float4(a.x, a.y, b.x, b.y);
        o4[1] = make_float4(c.x, c.y, d.x, d.y);
    }
}

// ---------------------------------------------------------------------------
extern "C" void kernel_launch(void* const* d_in, const int* in_sizes, int n_in,
                              void* d_out, int out_size) {
    const float* features = (const float*)d_in[0];
    const float* rois     = (const float*)d_in[1];
    float*       out      = (float*)d_out;
    const int n_rois = in_sizes[1] / 5;

    cudaFuncSetAttribute(roi_plus_avg_kernel,
                         cudaFuncAttributeMaxDynamicSharedMemorySize,
                         SMEM_BYTES);

    dim3 tgrid((HW + 31) / 32, CH / 32, BATCH);
    dim3 tblk(32, 8);
    transpose_nchw_nhwc<<<tgrid, tblk>>>(features);

    roi_plus_avg_kernel<<<n_rois, NTHREADS, SMEM_BYTES>>>(rois, out);
}

// round 11
// speedup vs baseline: 1.0354x; 1.0354x over previous
#include <cuda_runtime.h>
#include <cuda_fp16.h>

#define BATCH 2
#define CH 512
#define FH 50
#define FW 75
#define HW (FH * FW)          // 3750
#define PH 8
#define PW 8
#define NTHREADS 256          // 2 channels per thread
#define OUT_PER_ROI (CH * 7 * 7)            // 25088 elements
#define SMEM_BYTES (OUT_PER_ROI * 2)        // 50176 bytes (fp16 staging)
#define SPATIAL_SCALE (1.0f / 16.0f)

// NHWC fp16 scratch: 2 * 3750 * 512 * 2B = 7.68 MB (deep in L2)
__device__ __half g_feat_hwc[BATCH * HW * CH];

// ---------------------------------------------------------------------------
// Kernel 1: NCHW fp32 -> NHWC fp16 transpose.
// ---------------------------------------------------------------------------
__global__ void transpose_nchw_nhwc(const float* __restrict__ in) {
    __shared__ float tile[32][33];
    const int b   = blockIdx.z;
    const int hw0 = blockIdx.x * 32;
    const int c0  = blockIdx.y * 32;

    const float* src = in + (size_t)b * CH * HW;
    __half*      dst = g_feat_hwc + (size_t)b * HW * CH;

    #pragma unroll
    for (int t = 0; t < 32; t += 8) {
        int c  = c0 + threadIdx.y + t;
        int hw = hw0 + threadIdx.x;
        if (hw < HW)
            tile[threadIdx.y + t][threadIdx.x] = src[(size_t)c * HW + hw];
    }
    __syncthreads();

    // Write phase: half2 over channel pairs, coalesced.
    const int tid = threadIdx.y * 32 + threadIdx.x;   // 0..255
    #pragma unroll
    for (int t = 0; t < 2; t++) {
        const int idx    = t * 256 + tid;   // 0..511
        const int hw_off = idx >> 4;        // 0..31
        const int cpair  = idx & 15;        // 0..15
        const int hw     = hw0 + hw_off;
        if (hw < HW) {
            __half2 v = __floats2half2_rn(tile[2 * cpair][hw_off],
                                          tile[2 * cpair + 1][hw_off]);
            *(__half2*)(dst + (size_t)hw * CH + c0 + 2 * cpair) = v;
        }
    }
}

// ---------------------------------------------------------------------------
// Kernel 2: one CTA per roi, 256 threads = 2 consecutive channels each.
// half2 loads (LDG.32) on NHWC fp16; fp32 interpolation + pooling; output
// staged in fp16 smem (conflict-free), copied out coalesced as fp32.
// ---------------------------------------------------------------------------
__global__ __launch_bounds__(NTHREADS, 4)
void roi_plus_avg_kernel(const float* __restrict__ rois,
                         float* __restrict__ out) {
    extern __shared__ __half s_out[];   // OUT_PER_ROI halves

    const int n  = blockIdx.x;
    const int c0 = threadIdx.x * 2;     // channels c0, c0+1

    __shared__ int   s_hs[PH], s_ws[PW];
    __shared__ float s_hr[PH], s_wr[PW];
    __shared__ int   s_hv[PH], s_wv[PW];
    __shared__ int   s_b;

    if (threadIdx.x < PH) {
        const int i = threadIdx.x;
        const float x1 = rois[n * 5 + 1] * SPATIAL_SCALE;
        const float y1 = rois[n * 5 + 2] * SPATIAL_SCALE;
        const float x2 = rois[n * 5 + 3] * SPATIAL_SCALE;
        const float y2 = rois[n * 5 + 4] * SPATIAL_SCALE;
        const float roi_w = fmaxf(x2 - x1 + 1.0f, 0.0f);
        const float roi_h = fmaxf(y2 - y1 + 1.0f, 0.0f);
        const float bin_h = roi_h * (1.0f / (PH - 1));
        const float bin_w = roi_w * (1.0f / (PW - 1));

        const float hh = y1 + (float)i * bin_h;
        const float ww = x1 + (float)i * bin_w;

        s_hv[i] = (hh >= 0.0f) && (hh < (float)FH);
        s_wv[i] = (ww >= 0.0f) && (ww < (float)FW);

        int hs = (int)floorf(hh);
        int ws = (int)floorf(ww);
        hs = min(max(hs, 0), FH - 2);
        ws = min(max(ws, 0), FW - 2);
        s_hs[i] = hs;
        s_ws[i] = ws;
        s_hr[i] = hh - (float)hs;
        s_wr[i] = ww - (float)ws;

        if (i == 0) s_b = (int)rois[n * 5 + 0];
    }
    __syncthreads();

    const __half* fb = g_feat_hwc + (size_t)s_b * HW * CH + c0;

    float2 prev[PW];
    float2 cur[PW];

    #pragma unroll
    for (int i = 0; i < PH; i++) {
        const int   hs = s_hs[i];
        const float hr = s_hr[i];
        const bool  hv = (s_hv[i] != 0);
        const __half* r0 = fb + (size_t)(hs * FW) * CH;
        const __half* r1 = r0 + (size_t)FW * CH;

        #pragma unroll
        for (int j = 0; j < PW; j++) {
            float2 v = make_float2(0.0f, 0.0f);
            if (hv && s_wv[j]) {
                const int   ws = s_ws[j];
                const float wr = s_wr[j];
                const float2 ul = __half22float2(__ldg((const __half2*)(r0 + (size_t)ws * CH)));
                const float2 ur = __half22float2(__ldg((const __half2*)(r0 + (size_t)(ws + 1) * CH)));
                const float2 ll = __half22float2(__ldg((const __half2*)(r1 + (size_t)ws * CH)));
                const float2 lr = __half22float2(__ldg((const __half2*)(r1 + (size_t)(ws + 1) * CH)));
                const float tx = fmaf(ur.x - ul.x, wr, ul.x);
                const float bx = fmaf(lr.x - ll.x, wr, ll.x);
                const float ty = fmaf(ur.y - ul.y, wr, ul.y);
                const float by = fmaf(lr.y - ll.y, wr, ll.y);
                v.x = fmaf(bx - tx, hr, tx);
                v.y = fmaf(by - ty, hr, ty);
            }
            cur[j] = v;
        }

        if (i > 0) {
            // fp16 staging, per-channel stride 49 halves -> odd word stride,
            // conflict-free STS.16
            __half* o0 = s_out + c0 * 49 + (i - 1) * 7;
            __half* o1 = o0 + 49;
            #pragma unroll
            for (int j = 0; j < 7; j++) {
                o0[j] = __float2half_rn(0.25f * (prev[j].x + prev[j + 1].x +
                                                 cur[j].x  + cur[j + 1].x));
                o1[j] = __float2half_rn(0.25f * (prev[j].y + prev[j + 1].y +
                                                 cur[j].y  + cur[j + 1].y));
            }
        }
        #pragma unroll
        for (int j = 0; j < PW; j++) prev[j] = cur[j];
    }

    __syncthreads();

    // Coalesced copy-out: read 8 halves (uint4), write 2 float4.
    // 25088 halves = 3136 uint4 chunks.
    float*        dstf = out + (size_t)n * OUT_PER_ROI;
    const uint4*  src  = (const uint4*)s_out;
    for (int idx = threadIdx.x; idx < OUT_PER_ROI / 8; idx += NTHREADS) {
        const uint4 u = src[idx];
        const float2 a = __half22float2(*(const __half2*)&u.x);
        const float2 b = __half22float2(*(const __half2*)&u.y);
        const float2 c = __half22float2(*(const __half2*)&u.z);
        const float2 d = __half22float2(*(const __half2*)&u.w);
        float4* o4 = (float4*)(dstf + idx * 8);
        o4[0] = make_float4(a.x, a.y, b.x, b.y);
        o4[1] = make_float4(c.x, c.y, d.x, d.y);
    }
}

// ---------------------------------------------------------------------------
extern "C" void kernel_launch(void* const* d_in, const int* in_sizes, int n_in,
                              void* d_out, int out_size) {
    const float* features = (const float*)d_in[0];
    const float* rois     = (const float*)d_in[1];
    float*       out      = (float*)d_out;
    const int n_rois = in_sizes[1] / 5;

    cudaFuncSetAttribute(roi_plus_avg_kernel,
                         cudaFuncAttributeMaxDynamicSharedMemorySize,
                         SMEM_BYTES);

    dim3 tgrid((HW + 31) / 32, CH / 32, BATCH);
    dim3 tblk(32, 8);
    transpose_nchw_nhwc<<<tgrid, tblk>>>(features);

    roi_plus_avg_kernel<<<n_rois, NTHREADS, SMEM_BYTES>>>(rois, out);
}

// round 12
// speedup vs baseline: 1.1992x; 1.1582x over previous
#include <cuda_runtime.h>
#include <cuda_fp16.h>

#define BATCH 2
#define CH 512
#define FH 50
#define FW 75
#define HW (FH * FW)          // 3750
#define PH 8
#define PW 8
#define NTHREADS 256          // 2 channels per thread
#define OUT_PER_ROI (CH * 7 * 7)            // 25088 elements
#define SMEM_BYTES (OUT_PER_ROI * 2)        // 50176 bytes (fp16 staging)
#define SPATIAL_SCALE (1.0f / 16.0f)

// NHWC fp32 scratch: 2 * 3750 * 512 * 4B = 15.36 MB (fits L2)
__device__ float g_feat_hwc[BATCH * HW * CH];

// ---------------------------------------------------------------------------
// Kernel 1: NCHW -> NHWC transpose (fp32, as in R6).
// ---------------------------------------------------------------------------
__global__ void transpose_nchw_nhwc(const float* __restrict__ in) {
    __shared__ float tile[32][33];
    const int b   = blockIdx.z;
    const int hw0 = blockIdx.x * 32;
    const int c0  = blockIdx.y * 32;

    const float* src = in + (size_t)b * CH * HW;
    float*       dst = g_feat_hwc + (size_t)b * HW * CH;

    #pragma unroll
    for (int t = 0; t < 32; t += 8) {
        int c  = c0 + threadIdx.y + t;
        int hw = hw0 + threadIdx.x;
        if (hw < HW)
            tile[threadIdx.y + t][threadIdx.x] = src[(size_t)c * HW + hw];
    }
    __syncthreads();
    #pragma unroll
    for (int t = 0; t < 32; t += 8) {
        int hw = hw0 + threadIdx.y + t;
        int c  = c0 + threadIdx.x;
        if (hw < HW)
            dst[(size_t)hw * CH + c] = tile[threadIdx.x][threadIdx.y + t];
    }
}

// ---------------------------------------------------------------------------
// Kernel 2: one CTA per roi, 256 threads = 2 consecutive channels each.
// fp32 LDG.64 loads on NHWC (R6 load path), fp32 interpolation + pooling,
// output staged in fp16 smem (conflict-free odd stride, 50 KB -> 3 CTAs/SM),
// coalesced fp32 copy-out.
// ---------------------------------------------------------------------------
__global__ __launch_bounds__(NTHREADS, 3)
void roi_plus_avg_kernel(const float* __restrict__ rois,
                         float* __restrict__ out) {
    extern __shared__ __half s_out[];   // OUT_PER_ROI halves

    const int n  = blockIdx.x;
    const int c0 = threadIdx.x * 2;     // channels c0, c0+1

    __shared__ int   s_hs[PH], s_ws[PW];
    __shared__ float s_hr[PH], s_wr[PW];
    __shared__ int   s_hv[PH], s_wv[PW];
    __shared__ int   s_b;

    if (threadIdx.x < PH) {
        const int i = threadIdx.x;
        const float x1 = rois[n * 5 + 1] * SPATIAL_SCALE;
        const float y1 = rois[n * 5 + 2] * SPATIAL_SCALE;
        const float x2 = rois[n * 5 + 3] * SPATIAL_SCALE;
        const float y2 = rois[n * 5 + 4] * SPATIAL_SCALE;
        const float roi_w = fmaxf(x2 - x1 + 1.0f, 0.0f);
        const float roi_h = fmaxf(y2 - y1 + 1.0f, 0.0f);
        const float bin_h = roi_h * (1.0f / (PH - 1));
        const float bin_w = roi_w * (1.0f / (PW - 1));

        const float hh = y1 + (float)i * bin_h;
        const float ww = x1 + (float)i * bin_w;

        s_hv[i] = (hh >= 0.0f) && (hh < (float)FH);
        s_wv[i] = (ww >= 0.0f) && (ww < (float)FW);

        int hs = (int)floorf(hh);
        int ws = (int)floorf(ww);
        hs = min(max(hs, 0), FH - 2);
        ws = min(max(ws, 0), FW - 2);
        s_hs[i] = hs;
        s_ws[i] = ws;
        s_hr[i] = hh - (float)hs;
        s_wr[i] = ww - (float)ws;

        if (i == 0) s_b = (int)rois[n * 5 + 0];
    }
    __syncthreads();

    const float* fb = g_feat_hwc + (size_t)s_b * HW * CH + c0;

    float2 prev[PW];
    float2 cur[PW];

    #pragma unroll
    for (int i = 0; i < PH; i++) {
        const int   hs = s_hs[i];
        const float hr = s_hr[i];
        const bool  hv = (s_hv[i] != 0);
        const float* r0 = fb + (size_t)(hs * FW) * CH;
        const float* r1 = r0 + (size_t)FW * CH;

        #pragma unroll
        for (int j = 0; j < PW; j++) {
            float2 v = make_float2(0.0f, 0.0f);
            if (hv && s_wv[j]) {
                const int   ws = s_ws[j];
                const float wr = s_wr[j];
                const float2 ul = __ldg((const float2*)(r0 + (size_t)ws * CH));
                const float2 ur = __ldg((const float2*)(r0 + (size_t)(ws + 1) * CH));
                const float2 ll = __ldg((const float2*)(r1 + (size_t)ws * CH));
                const float2 lr = __ldg((const float2*)(r1 + (size_t)(ws + 1) * CH));
                const float tx = fmaf(ur.x - ul.x, wr, ul.x);
                const float bx = fmaf(lr.x - ll.x, wr, ll.x);
                const float ty = fmaf(ur.y - ul.y, wr, ul.y);
                const float by = fmaf(lr.y - ll.y, wr, ll.y);
                v.x = fmaf(bx - tx, hr, tx);
                v.y = fmaf(by - ty, hr, ty);
            }
            cur[j] = v;
        }

        if (i > 0) {
            // fp16 staging: channel stride 49 halves (odd word stride ->
            // conflict-free STS.16)
            __half* o0 = s_out + c0 * 49 + (i - 1) * 7;
            __half* o1 = o0 + 49;
            #pragma unroll
            for (int j = 0; j < 7; j++) {
                o0[j] = __float2half_rn(0.25f * (prev[j].x + prev[j + 1].x +
                                                 cur[j].x  + cur[j + 1].x));
                o1[j] = __float2half_rn(0.25f * (prev[j].y + prev[j + 1].y +
                                                 cur[j].y  + cur[j + 1].y));
            }
        }
        #pragma unroll
        for (int j = 0; j < PW; j++) prev[j] = cur[j];
    }

    __syncthreads();

    // Coalesced copy-out: read 8 halves (uint4), write 2 float4.
    // 25088 halves = 3136 uint4 chunks.
    float*       dstf = out + (size_t)n * OUT_PER_ROI;
    const uint4* src  = (const uint4*)s_out;
    for (int idx = threadIdx.x; idx < OUT_PER_ROI / 8; idx += NTHREADS) {
        const uint4 u = src[idx];
        const float2 a = __half22float2(*(const __half2*)&u.x);
        const float2 b = __half22float2(*(const __half2*)&u.y);
        const float2 c = __half22float2(*(const __half2*)&u.z);
        const float2 d = __half22float2(*(const __half2*)&u.w);
        float4* o4 = (float4*)(dstf + idx * 8);
        o4[0] = make_float4(a.x, a.y, b.x, b.y);
        o4[1] = make_float4(c.x, c.y, d.x, d.y);
    }
}

// ---------------------------------------------------------------------------
extern "C" void kernel_launch(void* const* d_in, const int* in_sizes, int n_in,
                              void* d_out, int out_size) {
    const float* features = (const float*)d_in[0];
    const float* rois     = (const float*)d_in[1];
    float*       out      = (float*)d_out;
    const int n_rois = in_sizes[1] / 5;

    cudaFuncSetAttribute(roi_plus_avg_kernel,
                         cudaFuncAttributeMaxDynamicSharedMemorySize,
                         SMEM_BYTES);

    dim3 tgrid((HW + 31) / 32, CH / 32, BATCH);
    dim3 tblk(32, 8);
    transpose_nchw_nhwc<<<tgrid, tblk>>>(features);

    roi_plus_avg_kernel<<<n_rois, NTHREADS, SMEM_BYTES>>>(rois, out);
}

// round 13
// speedup vs baseline: 1.4307x; 1.1930x over previous
#include <cuda_runtime.h>
#include <cuda_fp16.h>

#define BATCH 2
#define CH 512
#define FH 50
#define FW 75
#define HW (FH * FW)          // 3750
#define PH 8
#define PW 8
#define NTHREADS 256          // 2 channels per thread (packed half2)
#define OUT_PER_ROI (CH * 7 * 7)            // 25088 elements
#define SMEM_BYTES (OUT_PER_ROI * 2)        // 50176 bytes (fp16 staging)
#define SPATIAL_SCALE (1.0f / 16.0f)

// NHWC fp16 scratch: 2 * 3750 * 512 * 2B = 7.68 MB (deep in L2)
__device__ __half g_feat_hwc[BATCH * HW * CH];

// ---------------------------------------------------------------------------
// Kernel 1: NCHW fp32 -> NHWC fp16 transpose.
// ---------------------------------------------------------------------------
__global__ void transpose_nchw_nhwc(const float* __restrict__ in) {
    __shared__ float tile[32][33];
    const int b   = blockIdx.z;
    const int hw0 = blockIdx.x * 32;
    const int c0  = blockIdx.y * 32;

    const float* src = in + (size_t)b * CH * HW;
    __half*      dst = g_feat_hwc + (size_t)b * HW * CH;

    #pragma unroll
    for (int t = 0; t < 32; t += 8) {
        int c  = c0 + threadIdx.y + t;
        int hw = hw0 + threadIdx.x;
        if (hw < HW)
            tile[threadIdx.y + t][threadIdx.x] = src[(size_t)c * HW + hw];
    }
    __syncthreads();

    const int tid = threadIdx.y * 32 + threadIdx.x;   // 0..255
    #pragma unroll
    for (int t = 0; t < 2; t++) {
        const int idx    = t * 256 + tid;   // 0..511
        const int hw_off = idx >> 4;        // 0..31
        const int cpair  = idx & 15;        // 0..15
        const int hw     = hw0 + hw_off;
        if (hw < HW) {
            __half2 v = __floats2half2_rn(tile[2 * cpair][hw_off],
                                          tile[2 * cpair + 1][hw_off]);
            *(__half2*)(dst + (size_t)hw * CH + c0 + 2 * cpair) = v;
        }
    }
}

// ---------------------------------------------------------------------------
// Kernel 2: one CTA per roi, 256 threads = 2 channels each (half2 packed).
// half2 loads + full half2 interpolation/pooling (no F2F on critical path),
// fp16 smem staging, coalesced fp32 copy-out.
// ---------------------------------------------------------------------------
__global__ __launch_bounds__(NTHREADS, 4)
void roi_plus_avg_kernel(const float* __restrict__ rois,
                         float* __restrict__ out) {
    extern __shared__ __half s_out[];   // OUT_PER_ROI halves

    const int n  = blockIdx.x;
    const int c0 = threadIdx.x * 2;     // channels c0, c0+1

    __shared__ int     s_hs[PH], s_ws[PW];
    __shared__ __half2 s_hr2[PH], s_wr2[PW];
    __shared__ int     s_hv[PH], s_wv[PW];
    __shared__ int     s_b;

    if (threadIdx.x < PH) {
        const int i = threadIdx.x;
        const float x1 = rois[n * 5 + 1] * SPATIAL_SCALE;
        const float y1 = rois[n * 5 + 2] * SPATIAL_SCALE;
        const float x2 = rois[n * 5 + 3] * SPATIAL_SCALE;
        const float y2 = rois[n * 5 + 4] * SPATIAL_SCALE;
        const float roi_w = fmaxf(x2 - x1 + 1.0f, 0.0f);
        const float roi_h = fmaxf(y2 - y1 + 1.0f, 0.0f);
        const float bin_h = roi_h * (1.0f / (PH - 1));
        const float bin_w = roi_w * (1.0f / (PW - 1));

        const float hh = y1 + (float)i * bin_h;
        const float ww = x1 + (float)i * bin_w;

        s_hv[i] = (hh >= 0.0f) && (hh < (float)FH);
        s_wv[i] = (ww >= 0.0f) && (ww < (float)FW);

        int hs = (int)floorf(hh);
        int ws = (int)floorf(ww);
        hs = min(max(hs, 0), FH - 2);
        ws = min(max(ws, 0), FW - 2);
        s_hs[i] = hs;
        s_ws[i] = ws;
        s_hr2[i] = __float2half2_rn(hh - (float)hs);
        s_wr2[i] = __float2half2_rn(ww - (float)ws);

        if (i == 0) s_b = (int)rois[n * 5 + 0];
    }
    __syncthreads();

    const __half* fb = g_feat_hwc + (size_t)s_b * HW * CH + c0;
    const __half2 zero2 = __float2half2_rn(0.0f);
    const __half2 quarter2 = __float2half2_rn(0.25f);

    __half2 prev[PW];
    __half2 cur[PW];

    #pragma unroll
    for (int i = 0; i < PH; i++) {
        const int     hs  = s_hs[i];
        const __half2 hr2 = s_hr2[i];
        const bool    hv  = (s_hv[i] != 0);
        const __half* r0 = fb + (size_t)(hs * FW) * CH;
        const __half* r1 = r0 + (size_t)FW * CH;

        #pragma unroll
        for (int j = 0; j < PW; j++) {
            __half2 v = zero2;
            if (hv && s_wv[j]) {
                const int     ws  = s_ws[j];
                const __half2 wr2 = s_wr2[j];
                const __half2 ul = __ldg((const __half2*)(r0 + (size_t)ws * CH));
                const __half2 ur = __ldg((const __half2*)(r0 + (size_t)(ws + 1) * CH));
                const __half2 ll = __ldg((const __half2*)(r1 + (size_t)ws * CH));
                const __half2 lr = __ldg((const __half2*)(r1 + (size_t)(ws + 1) * CH));
                const __half2 top = __hfma2(__hsub2(ur, ul), wr2, ul);
                const __half2 bot = __hfma2(__hsub2(lr, ll), wr2, ll);
                v = __hfma2(__hsub2(bot, top), hr2, top);
            }
            cur[j] = v;
        }

        if (i > 0) {
            // fp16 staging: channel stride 49 halves (odd word stride ->
            // conflict-free STS.16)
            __half* o0 = s_out + c0 * 49 + (i - 1) * 7;
            __half* o1 = o0 + 49;
            #pragma unroll
            for (int j = 0; j < 7; j++) {
                const __half2 s = __hmul2(
                    __hadd2(__hadd2(prev[j], prev[j + 1]),
                            __hadd2(cur[j],  cur[j + 1])),
                    quarter2);
                o0[j] = __low2half(s);
                o1[j] = __high2half(s);
            }
        }
        #pragma unroll
        for (int j = 0; j < PW; j++) prev[j] = cur[j];
    }

    __syncthreads();

    // Coalesced copy-out: read 8 halves (uint4), write 2 float4.
    // 25088 halves = 3136 uint4 chunks.
    float*       dstf = out + (size_t)n * OUT_PER_ROI;
    const uint4* src  = (const uint4*)s_out;
    for (int idx = threadIdx.x; idx < OUT_PER_ROI / 8; idx += NTHREADS) {
        const uint4 u = src[idx];
        const float2 a = __half22float2(*(const __half2*)&u.x);
        const float2 b = __half22float2(*(const __half2*)&u.y);
        const float2 c = __half22float2(*(const __half2*)&u.z);
        const float2 d = __half22float2(*(const __half2*)&u.w);
        float4* o4 = (float4*)(dstf + idx * 8);
        o4[0] = make_float4(a.x, a.y, b.x, b.y);
        o4[1] = make_float4(c.x, c.y, d.x, d.y);
    }
}

// ---------------------------------------------------------------------------
extern "C" void kernel_launch(void* const* d_in, const int* in_sizes, int n_in,
                              void* d_out, int out_size) {
    const float* features = (const float*)d_in[0];
    const float* rois     = (const float*)d_in[1];
    float*       out      = (float*)d_out;
    const int n_rois = in_sizes[1] / 5;

    cudaFuncSetAttribute(roi_plus_avg_kernel,
                         cudaFuncAttributeMaxDynamicSharedMemorySize,
                         SMEM_BYTES);

    dim3 tgrid((HW + 31) / 32, CH / 32, BATCH);
    dim3 tblk(32, 8);
    transpose_nchw_nhwc<<<tgrid, tblk>>>(features);

    roi_plus_avg_kernel<<<n_rois, NTHREADS, SMEM_BYTES>>>(rois, out);
}

// round 14
// speedup vs baseline: 1.5439x; 1.0791x over previous
#include <cuda_runtime.h>
#include <cuda_fp16.h>

#define BATCH 2
#define CH 512
#define FH 50
#define FW 75
#define HW (FH * FW)          // 3750
#define PH 8
#define PW 8
#define NTHREADS 128          // 2 channels per thread, 256 channels per CTA
#define CH_PER_CTA 256
#define OUT_PER_ROI (CH * 7 * 7)            // 25088 elements
#define OUT_PER_CTA (CH_PER_CTA * 7 * 7)    // 12544 elements
#define SMEM_BYTES (OUT_PER_CTA * 2)        // 25088 bytes (fp16 staging)
#define SPATIAL_SCALE (1.0f / 16.0f)

// NHWC fp16 scratch: 2 * 3750 * 512 * 2B = 7.68 MB (deep in L2)
__device__ __half g_feat_hwc[BATCH * HW * CH];

// ---------------------------------------------------------------------------
// Kernel 1: NCHW fp32 -> NHWC fp16 transpose.
// ---------------------------------------------------------------------------
__global__ void transpose_nchw_nhwc(const float* __restrict__ in) {
    __shared__ float tile[32][33];
    const int b   = blockIdx.z;
    const int hw0 = blockIdx.x * 32;
    const int c0  = blockIdx.y * 32;

    const float* src = in + (size_t)b * CH * HW;
    __half*      dst = g_feat_hwc + (size_t)b * HW * CH;

    #pragma unroll
    for (int t = 0; t < 32; t += 8) {
        int c  = c0 + threadIdx.y + t;
        int hw = hw0 + threadIdx.x;
        if (hw < HW)
            tile[threadIdx.y + t][threadIdx.x] = src[(size_t)c * HW + hw];
    }
    __syncthreads();

    const int tid = threadIdx.y * 32 + threadIdx.x;   // 0..255
    #pragma unroll
    for (int t = 0; t < 2; t++) {
        const int idx    = t * 256 + tid;   // 0..511
        const int hw_off = idx >> 4;        // 0..31
        const int cpair  = idx & 15;        // 0..15
        const int hw     = hw0 + hw_off;
        if (hw < HW) {
            __half2 v = __floats2half2_rn(tile[2 * cpair][hw_off],
                                          tile[2 * cpair + 1][hw_off]);
            *(__half2*)(dst + (size_t)hw * CH + c0 + 2 * cpair) = v;
        }
    }
}

// ---------------------------------------------------------------------------
// Kernel 2: grid (n_rois, 2). Each CTA = half a roi's channels.
// 128 threads = 2 channels each (half2 packed). half2 loads + half2
// interpolation/pooling, fp16 smem staging (24.5 KB -> 9 CTAs/SM),
// coalesced fp32 copy-out.
// ---------------------------------------------------------------------------
__global__ __launch_bounds__(NTHREADS, 9)
void roi_plus_avg_kernel(const float* __restrict__ rois,
                         float* __restrict__ out) {
    extern __shared__ __half s_out[];   // OUT_PER_CTA halves

    const int n     = blockIdx.x;
    const int half  = blockIdx.y;                  // channel half: 0 or 1
    const int cbase = half * CH_PER_CTA;
    const int cloc  = threadIdx.x * 2;             // local channel pair
    const int c0    = cbase + cloc;                // global channel

    __shared__ int     s_hs[PH], s_ws[PW];
    __shared__ __half2 s_hr2[PH], s_wr2[PW];
    __shared__ int     s_hv[PH], s_wv[PW];
    __shared__ int     s_b;

    if (threadIdx.x < PH) {
        const int i = threadIdx.x;
        const float x1 = rois[n * 5 + 1] * SPATIAL_SCALE;
        const float y1 = rois[n * 5 + 2] * SPATIAL_SCALE;
        const float x2 = rois[n * 5 + 3] * SPATIAL_SCALE;
        const float y2 = rois[n * 5 + 4] * SPATIAL_SCALE;
        const float roi_w = fmaxf(x2 - x1 + 1.0f, 0.0f);
        const float roi_h = fmaxf(y2 - y1 + 1.0f, 0.0f);
        const float bin_h = roi_h * (1.0f / (PH - 1));
        const float bin_w = roi_w * (1.0f / (PW - 1));

        const float hh = y1 + (float)i * bin_h;
        const float ww = x1 + (float)i * bin_w;

        s_hv[i] = (hh >= 0.0f) && (hh < (float)FH);
        s_wv[i] = (ww >= 0.0f) && (ww < (float)FW);

        int hs = (int)floorf(hh);
        int ws = (int)floorf(ww);
        hs = min(max(hs, 0), FH - 2);
        ws = min(max(ws, 0), FW - 2);
        s_hs[i] = hs;
        s_ws[i] = ws;
        s_hr2[i] = __float2half2_rn(hh - (float)hs);
        s_wr2[i] = __float2half2_rn(ww - (float)ws);

        if (i == 0) s_b = (int)rois[n * 5 + 0];
    }
    __syncthreads();

    const __half* fb = g_feat_hwc + (size_t)s_b * HW * CH + c0;
    const __half2 zero2 = __float2half2_rn(0.0f);
    const __half2 quarter2 = __float2half2_rn(0.25f);

    __half2 prev[PW];
    __half2 cur[PW];

    #pragma unroll
    for (int i = 0; i < PH; i++) {
        const int     hs  = s_hs[i];
        const __half2 hr2 = s_hr2[i];
        const bool    hv  = (s_hv[i] != 0);
        const __half* r0 = fb + (size_t)(hs * FW) * CH;
        const __half* r1 = r0 + (size_t)FW * CH;

        #pragma unroll
        for (int j = 0; j < PW; j++) {
            __half2 v = zero2;
            if (hv && s_wv[j]) {
                const int     ws  = s_ws[j];
                const __half2 wr2 = s_wr2[j];
                const __half2 ul = __ldg((const __half2*)(r0 + (size_t)ws * CH));
                const __half2 ur = __ldg((const __half2*)(r0 + (size_t)(ws + 1) * CH));
                const __half2 ll = __ldg((const __half2*)(r1 + (size_t)ws * CH));
                const __half2 lr = __ldg((const __half2*)(r1 + (size_t)(ws + 1) * CH));
                const __half2 top = __hfma2(__hsub2(ur, ul), wr2, ul);
                const __half2 bot = __hfma2(__hsub2(lr, ll), wr2, ll);
                v = __hfma2(__hsub2(bot, top), hr2, top);
            }
            cur[j] = v;
        }

        if (i > 0) {
            // fp16 staging: local channel stride 49 halves (odd word stride ->
            // conflict-free STS.16)
            __half* o0 = s_out + cloc * 49 + (i - 1) * 7;
            __half* o1 = o0 + 49;
            #pragma unroll
            for (int j = 0; j < 7; j++) {
                const __half2 s = __hmul2(
                    __hadd2(__hadd2(prev[j], prev[j + 1]),
                            __hadd2(cur[j],  cur[j + 1])),
                    quarter2);
                o0[j] = __low2half(s);
                o1[j] = __high2half(s);
            }
        }
        #pragma unroll
        for (int j = 0; j < PW; j++) prev[j] = cur[j];
    }

    __syncthreads();

    // Coalesced copy-out: read 8 halves (uint4), write 2 float4.
    // 12544 halves = 1568 uint4 chunks.
    float*       dstf = out + (size_t)n * OUT_PER_ROI + (size_t)cbase * 49;
    const uint4* src  = (const uint4*)s_out;
    for (int idx = threadIdx.x; idx < OUT_PER_CTA / 8; idx += NTHREADS) {
        const uint4 u = src[idx];
        const float2 a = __half22float2(*(const __half2*)&u.x);
        const float2 b = __half22float2(*(const __half2*)&u.y);
        const float2 c = __half22float2(*(const __half2*)&u.z);
        const float2 d = __half22float2(*(const __half2*)&u.w);
        float4* o4 = (float4*)(dstf + idx * 8);
        o4[0] = make_float4(a.x, a.y, b.x, b.y);
        o4[1] = make_float4(c.x, c.y, d.x, d.y);
    }
}

// ---------------------------------------------------------------------------
extern "C" void kernel_launch(void* const* d_in, const int* in_sizes, int n_in,
                              void* d_out, int out_size) {
    const float* features = (const float*)d_in[0];
    const float* rois     = (const float*)d_in[1];
    float*       out      = (float*)d_out;
    const int n_rois = in_sizes[1] / 5;

    cudaFuncSetAttribute(roi_plus_avg_kernel,
                         cudaFuncAttributeMaxDynamicSharedMemorySize,
                         SMEM_BYTES);

    dim3 tgrid((HW + 31) / 32, CH / 32, BATCH);
    dim3 tblk(32, 8);
    transpose_nchw_nhwc<<<tgrid, tblk>>>(features);

    dim3 rgrid(n_rois, 2);
    roi_plus_avg_kernel<<<rgrid, NTHREADS, SMEM_BYTES>>>(rois, out);
}